// round 14
// baseline (speedup 1.0000x reference)
#include <cuda_runtime.h>
#include <cuda_fp16.h>
#include <cstdint>

// ---------------------------------------------------------------------------
// FidelityLSTM: 2-layer LSTM (B=256, T=256, I=512, H=1024) + readout.
//
// Round-13: round-12 wavefront with STATIC placement-based tile partition
// (no atomics). Grid = 296 = 2x148; classic placement puts bid and bid+148
// on the same SM, so v = bid%148 owns tiles [v*384/148,(v+1)*384/148) and
// rank = bid/148 interleaves within that range. Worst SM = 3 tile-units
// (pipe-bound ~28us) vs round-12's 4 (36.8us).
//   tile tk: z = tk>>7 (0: layer-0 step t=i, 1: xg1 GEMM t=i-1,
//            2: layer-1 step t=i-2), nt = tk&31, mtl = (tk&127)>>5.
// fp16 m16n8k16 mma.sync, fp32 accum, 3-stage cp.async, gate-interleaved
// p=4j+g weights. Numerics identical to all passing rounds.
// ---------------------------------------------------------------------------

#define BB   256
#define TT   256
#define II   512
#define HH   1024
#define G4H  4096

#define NSTAGE 3
#define SS_H   7680          // halves per stage: A 64x40 + B 128x40
#define NWAVE  (TT + 2)
#define NSM    148
#define NTILE  384

// ------------------------- scratch (device globals) ------------------------
// W blocks: [128 n][32 k] halves, 4096 halves each, index (nt*NKP+kp).
// A blocks: [64 rows][32 k] halves, 2048 halves each, index (mt*NKP+kp).
__device__ __align__(16) __half g_Wih0p[(size_t)G4H * II];
__device__ __align__(16) __half g_Whh0p[(size_t)G4H * HH];
__device__ __align__(16) __half g_Wih1p[(size_t)G4H * HH];
__device__ __align__(16) __half g_Whh1p[(size_t)G4H * HH];
__device__ float g_b0p[G4H];
__device__ float g_b1p[G4H];
__device__ __align__(16) __half g_ctxp[(size_t)BB * TT * II];
__device__ __align__(16) __half g_hA0[2][BB * HH];
__device__ __align__(16) __half g_hA1[2][BB * HH];
__device__ float g_c0[BB * HH];
__device__ float g_c1[BB * HH];
__device__ float g_xg0[(size_t)BB * TT * G4H];
__device__ float g_xg1[2][(size_t)BB * G4H];

// ------------------------------ helpers ------------------------------------
__device__ __forceinline__ float sigmoidf_(float x) {
    return 1.f / (1.f + __expf(-x));
}

__device__ __forceinline__ void cpa16(const __half* dst, const __half* src) {
    uint32_t d = (uint32_t)__cvta_generic_to_shared(dst);
    asm volatile("cp.async.cg.shared.global [%0], [%1], 16;\n"
                 :: "r"(d), "l"(src));
}

__device__ __forceinline__ void ldsm4(uint32_t r[4], const __half* p) {
    uint32_t a = (uint32_t)__cvta_generic_to_shared(p);
    asm volatile("ldmatrix.sync.aligned.m8n8.x4.shared.b16 {%0,%1,%2,%3}, [%4];"
                 : "=r"(r[0]), "=r"(r[1]), "=r"(r[2]), "=r"(r[3]) : "r"(a));
}

__device__ __forceinline__ void mma16(float d[4], const uint32_t a[4],
                                      uint32_t b0, uint32_t b1) {
    asm volatile(
        "mma.sync.aligned.m16n8k16.row.col.f32.f16.f16.f32 "
        "{%0,%1,%2,%3}, {%4,%5,%6,%7}, {%8,%9}, {%0,%1,%2,%3};"
        : "+f"(d[0]), "+f"(d[1]), "+f"(d[2]), "+f"(d[3])
        : "r"(a[0]), "r"(a[1]), "r"(a[2]), "r"(a[3]), "r"(b0), "r"(b1));
}

// ---------------------------------------------------------------------------
// GEMM mainloop (proven): C[64 x 128], A blocks [64x32], B blocks [128x32].
// 256 threads, 8 warps = 2(m) x 4(n), warp tile 32x32.
// 3-stage cp.async pipeline, 1 sync/panel.
// ---------------------------------------------------------------------------
__device__ __forceinline__ void gemm16(
    const __half* __restrict__ Ablk, const __half* __restrict__ Bblk,
    int NKP, __half* sm, float acc[2][4][4])
{
    const int tid  = threadIdx.x;
    const int lane = tid & 31;
    const int warp = tid >> 5;
    const int wm   = warp >> 2;   // 0..1
    const int wn   = warp & 3;    // 0..3

    const int ar = tid >> 2;            // 0..63
    const int ac = (tid & 3) * 8;       // 0,8,16,24

#define FILL_P(kp, s) do {                                                  \
        const __half* ga = Ablk + (size_t)(kp) * 2048;                      \
        const __half* gb = Bblk + (size_t)(kp) * 4096;                      \
        __half* As_ = sm + (s) * SS_H;                                      \
        __half* Bs_ = As_ + 2560;                                           \
        cpa16(As_ + ar * 40 + ac, ga + ar * 32 + ac);                       \
        cpa16(Bs_ + ar * 40 + ac, gb + ar * 32 + ac);                       \
        cpa16(Bs_ + (ar + 64) * 40 + ac, gb + (ar + 64) * 32 + ac);         \
    } while (0)

    FILL_P(0, 0);
    asm volatile("cp.async.commit_group;\n");
    FILL_P(1, 1);
    asm volatile("cp.async.commit_group;\n");

    int s_c = 0, s_f = 2;
    for (int kp = 0; kp < NKP; kp++) {
        asm volatile("cp.async.wait_group 1;\n");
        __syncthreads();
        if (kp + 2 < NKP) FILL_P(kp + 2, s_f);
        asm volatile("cp.async.commit_group;\n");

        __half* Ac = sm + s_c * SS_H;
        __half* Bc = Ac + 2560;
        #pragma unroll
        for (int ks = 0; ks < 2; ks++) {
            uint32_t a[2][4];
            #pragma unroll
            for (int mf = 0; mf < 2; mf++) {
                int row = wm * 32 + mf * 16 + (lane & 7) + (lane & 8);
                int col = ks * 16 + ((lane >> 4) & 1) * 8;
                ldsm4(a[mf], Ac + row * 40 + col);
            }
            #pragma unroll
            for (int nfp = 0; nfp < 2; nfp++) {
                int row = wn * 32 + nfp * 16 + (lane & 7) + ((lane & 16) >> 1);
                int col = ks * 16 + (lane & 8);
                uint32_t b[4];
                ldsm4(b, Bc + row * 40 + col);
                mma16(acc[0][nfp * 2],     a[0], b[0], b[1]);
                mma16(acc[1][nfp * 2],     a[1], b[0], b[1]);
                mma16(acc[0][nfp * 2 + 1], a[0], b[2], b[3]);
                mma16(acc[1][nfp * 2 + 1], a[1], b[2], b[3]);
            }
        }
        if (++s_c == NSTAGE) s_c = 0;
        if (++s_f == NSTAGE) s_f = 0;
        __syncthreads();
    }
#undef FILL_P
}

// ---------------------------------------------------------------------------
// Bias epilogue (xg1 writes): dst[gm][gp] = acc + bias[gp]
// ---------------------------------------------------------------------------
__device__ __forceinline__ void bias_epi(
    float acc[2][4][4], float* __restrict__ dst, size_t row_stride,
    const float* __restrict__ bias, int m0, int p0)
{
    const int lane = threadIdx.x & 31;
    const int warp = threadIdx.x >> 5;
    const int wm = warp >> 2, wn = warp & 3;

    #pragma unroll
    for (int mf = 0; mf < 2; mf++) {
        int gm = m0 + wm * 32 + mf * 16 + (lane >> 2);
        #pragma unroll
        for (int nf = 0; nf < 4; nf++) {
            int gp = p0 + wn * 32 + nf * 8 + ((lane & 3) << 1);
            float b0v = bias[gp], b1v = bias[gp + 1];
            size_t base = (size_t)gm * row_stride + gp;
            dst[base]     = acc[mf][nf][0] + b0v;
            dst[base + 1] = acc[mf][nf][1] + b1v;
            size_t base2 = base + 8 * row_stride;
            dst[base2]     = acc[mf][nf][2] + b0v;
            dst[base2 + 1] = acc[mf][nf][3] + b1v;
        }
    }
}

// ---------------------------------------------------------------------------
// LSTM step epilogue: acc + xg -> gates -> cell update -> packed fp16 h.
// gs staging [64][132] floats in reused smem (33792B <= 46080B).
// ---------------------------------------------------------------------------
__device__ __forceinline__ void step_epi(
    float acc[2][4][4], float* gs,
    const float* __restrict__ xbase, size_t xstride,
    float* __restrict__ cbuf, __half* __restrict__ hout,
    int m0, int nt, int mtl)
{
    const int lane = threadIdx.x & 31;
    const int warp = threadIdx.x >> 5;
    const int wm = warp >> 2, wn = warp & 3;
    const int p0 = nt * 128;

    #pragma unroll
    for (int mf = 0; mf < 2; mf++) {
        int lm = wm * 32 + mf * 16 + (lane >> 2);
        #pragma unroll
        for (int nf = 0; nf < 4; nf++) {
            int lp = wn * 32 + nf * 8 + ((lane & 3) << 1);
            const float* x0 = xbase + (size_t)(m0 + lm) * xstride + p0 + lp;
            gs[lm * 132 + lp]     = acc[mf][nf][0] + x0[0];
            gs[lm * 132 + lp + 1] = acc[mf][nf][1] + x0[1];
            const float* x1 = xbase + (size_t)(m0 + lm + 8) * xstride + p0 + lp;
            gs[(lm + 8) * 132 + lp]     = acc[mf][nf][2] + x1[0];
            gs[(lm + 8) * 132 + lp + 1] = acc[mf][nf][3] + x1[1];
        }
    }
    __syncthreads();

    const int j0 = p0 >> 2;
    for (int it = threadIdx.x; it < 64 * 32; it += 256) {
        int lm = it >> 5;       // local batch row 0..63
        int lj = it & 31;       // local hidden unit 0..31
        float4 gv = *(float4*)(gs + lm * 132 + (lj << 2));
        int b = m0 + lm;
        int j = j0 + lj;
        float ig = sigmoidf_(gv.x);
        float fg = sigmoidf_(gv.y);
        float gg = tanhf(gv.z);
        float og = sigmoidf_(gv.w);
        int hc = b * HH + j;
        float c = fg * cbuf[hc] + ig * gg;
        cbuf[hc] = c;
        hout[(size_t)(mtl * 32 + nt) * 2048 + lm * 32 + lj] =
            __float2half_rn(og * tanhf(c));
    }
}

// ---------------------------------------------------------------------------
// Wavefront kernel, static placement-based partition (no atomics).
// grid = 296 CTAs x 256 threads; v = bid%148 owns tiles
// [v*384/148, (v+1)*384/148), rank = bid/148 interleaves within the range.
// ---------------------------------------------------------------------------
__global__ void __launch_bounds__(256, 2)
wave_kernel(int i)
{
    __shared__ __align__(16) __half sm[NSTAGE * SS_H];

    const int v    = (int)(blockIdx.x % NSM);
    const int rank = (int)(blockIdx.x / NSM);      // 0 or 1
    const int lo   = (v * NTILE) / NSM;
    const int hi   = ((v + 1) * NTILE) / NSM;

    for (int tk = lo + rank; tk < hi; tk += 2) {
        __syncthreads();              // smem (pipeline/gs) safe to reuse

        const int z    = tk >> 7;              // 0..2
        const int rest = tk & 127;
        const int nt   = rest & 31;            // 0..31
        const int mtl  = rest >> 5;            // 0..3
        const int m0   = mtl * 64;

        float acc[2][4][4];
        #pragma unroll
        for (int a = 0; a < 2; a++)
            #pragma unroll
            for (int b = 0; b < 4; b++)
                #pragma unroll
                for (int l = 0; l < 4; l++) acc[a][b][l] = 0.f;

        if (z == 0) {
            const int t = i;
            if (t >= TT) continue;
            gemm16(g_hA0[t & 1] + (size_t)mtl * 32 * 2048,
                   g_Whh0p + (size_t)nt * 32 * 4096, 32, sm, acc);
            step_epi(acc, (float*)sm,
                     g_xg0 + (size_t)t * G4H, (size_t)TT * G4H,
                     g_c0, g_hA0[(t + 1) & 1], m0, nt, mtl);
        } else if (z == 1) {
            const int t = i - 1;
            if (t < 0 || t >= TT) continue;
            gemm16(g_hA0[(t + 1) & 1] + (size_t)mtl * 32 * 2048,
                   g_Wih1p + (size_t)nt * 32 * 4096, 32, sm, acc);
            bias_epi(acc, g_xg1[t & 1], G4H, g_b1p, m0, nt * 128);
        } else {
            const int t = i - 2;
            if (t < 0) continue;
            gemm16(g_hA1[t & 1] + (size_t)mtl * 32 * 2048,
                   g_Whh1p + (size_t)nt * 32 * 4096, 32, sm, acc);
            step_epi(acc, (float*)sm,
                     g_xg1[t & 1], (size_t)G4H,
                     g_c1, g_hA1[(t + 1) & 1], m0, nt, mtl);
        }
    }
}

// ---------------------------------------------------------------------------
// Context input GEMM: xg0 = ctx @ Wih0^T + b0. grid (32, 1024), K=512.
// ---------------------------------------------------------------------------
__global__ void __launch_bounds__(256, 2)
ctx_gemm_kernel()
{
    __shared__ __align__(16) __half sm[NSTAGE * SS_H];

    const int nt = blockIdx.x;            // 0..31
    const int mt = blockIdx.y;            // 0..1023
    const int m0 = mt * 64;

    float acc[2][4][4];
    #pragma unroll
    for (int a = 0; a < 2; a++)
        #pragma unroll
        for (int b = 0; b < 4; b++)
            #pragma unroll
            for (int l = 0; l < 4; l++) acc[a][b][l] = 0.f;

    gemm16(g_ctxp + (size_t)mt * 16 * 2048,
           g_Wih0p + (size_t)nt * 16 * 4096, 16, sm, acc);

    bias_epi(acc, g_xg0, G4H, g_b0p, m0, nt * 128);
}

// ---------------------------------------------------------------------------
// Merged preprocessing: z 0-3 weights, z 4 context, z 5 biases + h/c init.
// W packed as [128 n][32 k] blocks, gate-interleaved p=4j+g.
// ---------------------------------------------------------------------------
__global__ void pack_all_kernel(
    const float* __restrict__ Wih0, const float* __restrict__ Whh0,
    const float* __restrict__ Wih1, const float* __restrict__ Whh1,
    const float* __restrict__ ctx,
    const float* __restrict__ bih0, const float* __restrict__ bhh0,
    const float* __restrict__ bih1, const float* __restrict__ bhh1,
    const float* __restrict__ init_h)
{
    const int z = blockIdx.z;
    const size_t stride = (size_t)gridDim.x * blockDim.x;
    size_t base = (size_t)blockIdx.x * blockDim.x + threadIdx.x;

    if (z < 4) {
        const float* src = (z == 0) ? Wih0 : (z == 1) ? Whh0
                         : (z == 2) ? Wih1 : Whh1;
        __half* dst = (z == 0) ? g_Wih0p : (z == 1) ? g_Whh0p
                    : (z == 2) ? g_Wih1p : g_Whh1p;
        const int K = (z == 0) ? II : HH;
        const int NKP = K >> 5;
        size_t n = (size_t)G4H * K;
        for (size_t idx = base; idx < n; idx += stride) {
            int blk = (int)(idx >> 12);          // 4096 halves per block
            int wi  = (int)(idx & 4095);
            int nl = wi >> 5, kl = wi & 31;
            int nt = blk / NKP, kp = blk % NKP;
            int p = nt * 128 + nl;
            int k = kp * 32 + kl;
            int j = p >> 2, g = p & 3;
            dst[idx] = __float2half_rn(src[(size_t)(g * HH + j) * K + k]);
        }
    } else if (z == 4) {
        size_t n = (size_t)BB * TT * II;
        for (size_t idx = base; idx < n; idx += stride) {
            int blk = (int)(idx >> 11);          // 2048 halves per block
            int wi  = (int)(idx & 2047);
            int r = wi >> 5, kl = wi & 31;
            int mt = blk >> 4, kp = blk & 15;    // NKP = 16
            size_t row = (size_t)mt * 64 + r;
            g_ctxp[idx] = __float2half_rn(ctx[row * II + kp * 32 + kl]);
        }
    } else {
        for (size_t p = base; p < G4H; p += stride) {
            int j = (int)(p >> 2), g = (int)(p & 3);
            int r = g * HH + j;
            g_b0p[p] = bih0[r] + bhh0[r];
            g_b1p[p] = bih1[r] + bhh1[r];
        }
        for (size_t i = base; i < (size_t)BB * HH; i += stride) {
            int b = (int)(i >> 10), j = (int)(i & 1023);
            size_t idx = (size_t)((b >> 6) * 32 + (j >> 5)) * 2048
                       + (b & 63) * 32 + (j & 31);
            __half hv = __float2half_rn(init_h[i]);
            g_hA0[0][idx] = hv;
            g_hA1[0][idx] = hv;
            g_c0[i] = 0.f;
            g_c1[i] = 0.f;
        }
    }
}

// readout: out[b] = h2_final[b] . W_ro + b_ro   (h2 final in g_hA1[0])
__global__ void readout_kernel(const float* __restrict__ Wro,
                               const float* __restrict__ bro,
                               float* __restrict__ out)
{
    int b = blockIdx.x;
    float s = 0.f;
    for (int j = threadIdx.x; j < HH; j += 128) {
        size_t idx = (size_t)((b >> 6) * 32 + (j >> 5)) * 2048
                   + (b & 63) * 32 + (j & 31);
        s += __half2float(g_hA1[0][idx]) * Wro[j];
    }
    #pragma unroll
    for (int o = 16; o; o >>= 1) s += __shfl_down_sync(0xffffffff, s, o);
    __shared__ float red[4];
    if ((threadIdx.x & 31) == 0) red[threadIdx.x >> 5] = s;
    __syncthreads();
    if (threadIdx.x == 0)
        out[b] = red[0] + red[1] + red[2] + red[3] + bro[0];
}

// ---------------------------------------------------------------------------
extern "C" void kernel_launch(void* const* d_in, const int* in_sizes, int n_in,
                              void* d_out, int out_size)
{
    const float* init_hidden = (const float*)d_in[0];
    const float* context     = (const float*)d_in[1];
    const float* W_ih0       = (const float*)d_in[2];
    const float* W_hh0       = (const float*)d_in[3];
    const float* b_ih0       = (const float*)d_in[4];
    const float* b_hh0       = (const float*)d_in[5];
    const float* W_ih1       = (const float*)d_in[6];
    const float* W_hh1       = (const float*)d_in[7];
    const float* b_ih1       = (const float*)d_in[8];
    const float* b_hh1       = (const float*)d_in[9];
    const float* W_ro        = (const float*)d_in[10];
    const float* b_ro        = (const float*)d_in[11];
    float* out = (float*)d_out;

    // launch 0: merged preprocessing
    pack_all_kernel<<<dim3(1024, 1, 6), 256>>>(
        W_ih0, W_hh0, W_ih1, W_hh1, context,
        b_ih0, b_hh0, b_ih1, b_hh1, init_hidden);

    // launch 1: layer-0 input gates (big parallel GEMM)
    ctx_gemm_kernel<<<dim3(32, (BB * TT) / 64), 256>>>();

    // launches 2..259: wavefront, 296 statically partitioned CTAs per tick
    for (int i = 0; i < NWAVE; i++)
        wave_kernel<<<296, 256>>>(i);

    // readout
    readout_kernel<<<BB, 128>>>(W_ro, b_ro, out);
}

// round 15
// speedup vs baseline: 1.3226x; 1.3226x over previous
#include <cuda_runtime.h>
#include <cuda_fp16.h>
#include <cstdint>

// ---------------------------------------------------------------------------
// FidelityLSTM: 2-layer LSTM (B=256, T=256, I=512, H=1024) + readout.
//
// Round-14: exact round-7 scheduling (the best measured: 258 launches of
// grid (32,4,3), 384 one-tile CTAs, hardware-distributed) with a K-panel=64
// mainloop: 16 panels/tile instead of 32 -> half the barrier/wait events,
// 2x longer fill bursts, same 3-stage depth (83KB dynamic smem, 2 CTAs/SM).
//   z=0: layer-0 step t=i   z=1: xg1 GEMM t=i-1   z=2: layer-1 step t=i-2
// fp16 m16n8k16 mma.sync, fp32 accum, gate-interleaved p=4j+g weights.
// Numerics identical to all passing rounds (rel_err 5.633e-4).
// ---------------------------------------------------------------------------

#define BB   256
#define TT   256
#define II   512
#define HH   1024
#define G4H  4096

#define NSTAGE 3
// per-stage smem halves: A 64 rows x 72 + B 128 rows x 72
#define SS_H   (64 * 72 + 128 * 72)      // 13824 halves = 27648 B
#define SMEMB  (NSTAGE * SS_H * 2)       // 82944 B dynamic smem
#define NWAVE  (TT + 2)

// ------------------------- scratch (device globals) ------------------------
// W blocks: [128 n][64 k] halves, 8192 halves each, index (nt*NKP+kp).
// A blocks: [64 rows][64 k] halves, 4096 halves each, index (mt*NKP+kp).
__device__ __align__(16) __half g_Wih0p[(size_t)G4H * II];
__device__ __align__(16) __half g_Whh0p[(size_t)G4H * HH];
__device__ __align__(16) __half g_Wih1p[(size_t)G4H * HH];
__device__ __align__(16) __half g_Whh1p[(size_t)G4H * HH];
__device__ float g_b0p[G4H];
__device__ float g_b1p[G4H];
__device__ __align__(16) __half g_ctxp[(size_t)BB * TT * II];
__device__ __align__(16) __half g_hA0[2][BB * HH];
__device__ __align__(16) __half g_hA1[2][BB * HH];
__device__ float g_c0[BB * HH];
__device__ float g_c1[BB * HH];
__device__ float g_xg0[(size_t)BB * TT * G4H];
__device__ float g_xg1[2][(size_t)BB * G4H];

// ------------------------------ helpers ------------------------------------
__device__ __forceinline__ float sigmoidf_(float x) {
    return 1.f / (1.f + __expf(-x));
}

__device__ __forceinline__ void cpa16(const __half* dst, const __half* src) {
    uint32_t d = (uint32_t)__cvta_generic_to_shared(dst);
    asm volatile("cp.async.cg.shared.global [%0], [%1], 16;\n"
                 :: "r"(d), "l"(src));
}

__device__ __forceinline__ void ldsm4(uint32_t r[4], const __half* p) {
    uint32_t a = (uint32_t)__cvta_generic_to_shared(p);
    asm volatile("ldmatrix.sync.aligned.m8n8.x4.shared.b16 {%0,%1,%2,%3}, [%4];"
                 : "=r"(r[0]), "=r"(r[1]), "=r"(r[2]), "=r"(r[3]) : "r"(a));
}

__device__ __forceinline__ void mma16(float d[4], const uint32_t a[4],
                                      uint32_t b0, uint32_t b1) {
    asm volatile(
        "mma.sync.aligned.m16n8k16.row.col.f32.f16.f16.f32 "
        "{%0,%1,%2,%3}, {%4,%5,%6,%7}, {%8,%9}, {%0,%1,%2,%3};"
        : "+f"(d[0]), "+f"(d[1]), "+f"(d[2]), "+f"(d[3])
        : "r"(a[0]), "r"(a[1]), "r"(a[2]), "r"(a[3]), "r"(b0), "r"(b1));
}

// ---------------------------------------------------------------------------
// GEMM mainloop: C[64 x 128], A blocks [64x64] (4096 h), B blocks [128x64]
// (8192 h). 256 threads, 8 warps = 2(m) x 4(n), warp tile 32x32.
// K-panel = 64 (4 mma k-steps), 3-stage cp.async pipeline, 1 sync/panel.
// smem rows padded to 72 halves (144B): row-to-row bank shift 4, 8 rows
// cover all 32 banks -> ldmatrix conflict-free.
// ---------------------------------------------------------------------------
__device__ __forceinline__ void gemm16(
    const __half* __restrict__ Ablk, const __half* __restrict__ Bblk,
    int NKP, __half* sm, float acc[2][4][4])
{
    const int tid  = threadIdx.x;
    const int lane = tid & 31;
    const int warp = tid >> 5;
    const int wm   = warp >> 2;   // 0..1
    const int wn   = warp & 3;    // 0..3

#define FILL_P(kp, s) do {                                                  \
        const __half* ga = Ablk + (size_t)(kp) * 4096;                      \
        const __half* gb = Bblk + (size_t)(kp) * 8192;                      \
        __half* As_ = sm + (s) * SS_H;                                      \
        __half* Bs_ = As_ + 64 * 72;                                        \
        _Pragma("unroll")                                                   \
        for (int q = 0; q < 2; q++) {                                       \
            int c = tid + q * 256;                                          \
            int r = c >> 3, col = (c & 7) * 8;                              \
            cpa16(As_ + r * 72 + col, ga + r * 64 + col);                   \
        }                                                                   \
        _Pragma("unroll")                                                   \
        for (int q = 0; q < 4; q++) {                                       \
            int c = tid + q * 256;                                          \
            int r = c >> 3, col = (c & 7) * 8;                              \
            cpa16(Bs_ + r * 72 + col, gb + r * 64 + col);                   \
        }                                                                   \
    } while (0)

    FILL_P(0, 0);
    asm volatile("cp.async.commit_group;\n");
    FILL_P(1, 1);
    asm volatile("cp.async.commit_group;\n");

    int s_c = 0, s_f = 2;
    for (int kp = 0; kp < NKP; kp++) {
        asm volatile("cp.async.wait_group 1;\n");
        __syncthreads();
        if (kp + 2 < NKP) FILL_P(kp + 2, s_f);
        asm volatile("cp.async.commit_group;\n");

        __half* Ac = sm + s_c * SS_H;
        __half* Bc = Ac + 64 * 72;
        #pragma unroll
        for (int ks = 0; ks < 4; ks++) {
            uint32_t a[2][4];
            #pragma unroll
            for (int mf = 0; mf < 2; mf++) {
                int row = wm * 32 + mf * 16 + (lane & 7) + (lane & 8);
                int col = ks * 16 + ((lane >> 4) & 1) * 8;
                ldsm4(a[mf], Ac + row * 72 + col);
            }
            #pragma unroll
            for (int nfp = 0; nfp < 2; nfp++) {
                int row = wn * 32 + nfp * 16 + (lane & 7) + ((lane & 16) >> 1);
                int col = ks * 16 + (lane & 8);
                uint32_t b[4];
                ldsm4(b, Bc + row * 72 + col);
                mma16(acc[0][nfp * 2],     a[0], b[0], b[1]);
                mma16(acc[1][nfp * 2],     a[1], b[0], b[1]);
                mma16(acc[0][nfp * 2 + 1], a[0], b[2], b[3]);
                mma16(acc[1][nfp * 2 + 1], a[1], b[2], b[3]);
            }
        }
        if (++s_c == NSTAGE) s_c = 0;
        if (++s_f == NSTAGE) s_f = 0;
        __syncthreads();
    }
#undef FILL_P
}

// ---------------------------------------------------------------------------
// Bias epilogue (xg writes): dst[gm][gp] = acc + bias[gp]
// ---------------------------------------------------------------------------
__device__ __forceinline__ void bias_epi(
    float acc[2][4][4], float* __restrict__ dst, size_t row_stride,
    const float* __restrict__ bias, int m0, int p0)
{
    const int lane = threadIdx.x & 31;
    const int warp = threadIdx.x >> 5;
    const int wm = warp >> 2, wn = warp & 3;

    #pragma unroll
    for (int mf = 0; mf < 2; mf++) {
        int gm = m0 + wm * 32 + mf * 16 + (lane >> 2);
        #pragma unroll
        for (int nf = 0; nf < 4; nf++) {
            int gp = p0 + wn * 32 + nf * 8 + ((lane & 3) << 1);
            float b0v = bias[gp], b1v = bias[gp + 1];
            size_t base = (size_t)gm * row_stride + gp;
            dst[base]     = acc[mf][nf][0] + b0v;
            dst[base + 1] = acc[mf][nf][1] + b1v;
            size_t base2 = base + 8 * row_stride;
            dst[base2]     = acc[mf][nf][2] + b0v;
            dst[base2 + 1] = acc[mf][nf][3] + b1v;
        }
    }
}

// ---------------------------------------------------------------------------
// LSTM step epilogue: acc + xg -> gates -> cell update -> packed fp16 h.
// gs staging [64][132] floats in reused dynamic smem (33792B <= 82944B).
// h[b][j] -> A image block (mtl*16 + (nt>>1)), row lm, k-col (nt&1)*32+lj.
// ---------------------------------------------------------------------------
__device__ __forceinline__ void step_epi(
    float acc[2][4][4], float* gs,
    const float* __restrict__ xbase, size_t xstride,
    float* __restrict__ cbuf, __half* __restrict__ hout,
    int m0, int nt, int mtl)
{
    const int lane = threadIdx.x & 31;
    const int warp = threadIdx.x >> 5;
    const int wm = warp >> 2, wn = warp & 3;
    const int p0 = nt * 128;

    #pragma unroll
    for (int mf = 0; mf < 2; mf++) {
        int lm = wm * 32 + mf * 16 + (lane >> 2);
        #pragma unroll
        for (int nf = 0; nf < 4; nf++) {
            int lp = wn * 32 + nf * 8 + ((lane & 3) << 1);
            const float* x0 = xbase + (size_t)(m0 + lm) * xstride + p0 + lp;
            gs[lm * 132 + lp]     = acc[mf][nf][0] + x0[0];
            gs[lm * 132 + lp + 1] = acc[mf][nf][1] + x0[1];
            const float* x1 = xbase + (size_t)(m0 + lm + 8) * xstride + p0 + lp;
            gs[(lm + 8) * 132 + lp]     = acc[mf][nf][2] + x1[0];
            gs[(lm + 8) * 132 + lp + 1] = acc[mf][nf][3] + x1[1];
        }
    }
    __syncthreads();

    const int j0 = p0 >> 2;
    __half* hblk = hout + (size_t)(mtl * 16 + (nt >> 1)) * 4096 + (nt & 1) * 32;
    for (int it = threadIdx.x; it < 64 * 32; it += 256) {
        int lm = it >> 5;       // local batch row 0..63
        int lj = it & 31;       // local hidden unit 0..31
        float4 gv = *(float4*)(gs + lm * 132 + (lj << 2));
        int b = m0 + lm;
        int j = j0 + lj;
        float ig = sigmoidf_(gv.x);
        float fg = sigmoidf_(gv.y);
        float gg = tanhf(gv.z);
        float og = sigmoidf_(gv.w);
        int hc = b * HH + j;
        float c = fg * cbuf[hc] + ig * gg;
        cbuf[hc] = c;
        hblk[lm * 64 + lj] = __float2half_rn(og * tanhf(c));
    }
}

// ---------------------------------------------------------------------------
// Wavefront kernel: grid (32 nt, 4 mtl, 3 z), 256 threads (R7 scheduling).
// ---------------------------------------------------------------------------
__global__ void __launch_bounds__(256, 2)
wave_kernel(int i)
{
    extern __shared__ __align__(16) __half sm[];

    const int z   = blockIdx.z;
    const int nt  = blockIdx.x;           // 0..31
    const int mtl = blockIdx.y;           // 0..3
    const int m0  = mtl * 64;

    float acc[2][4][4];
    #pragma unroll
    for (int a = 0; a < 2; a++)
        #pragma unroll
        for (int b = 0; b < 4; b++)
            #pragma unroll
            for (int l = 0; l < 4; l++) acc[a][b][l] = 0.f;

    if (z == 0) {
        const int t = i;
        if (t >= TT) return;
        gemm16(g_hA0[t & 1] + (size_t)mtl * 16 * 4096,
               g_Whh0p + (size_t)nt * 16 * 8192, 16, sm, acc);
        step_epi(acc, (float*)sm,
                 g_xg0 + (size_t)t * G4H, (size_t)TT * G4H,
                 g_c0, g_hA0[(t + 1) & 1], m0, nt, mtl);
    } else if (z == 1) {
        const int t = i - 1;
        if (t < 0 || t >= TT) return;
        gemm16(g_hA0[(t + 1) & 1] + (size_t)mtl * 16 * 4096,
               g_Wih1p + (size_t)nt * 16 * 8192, 16, sm, acc);
        bias_epi(acc, g_xg1[t & 1], G4H, g_b1p, m0, nt * 128);
    } else {
        const int t = i - 2;
        if (t < 0) return;
        gemm16(g_hA1[t & 1] + (size_t)mtl * 16 * 4096,
               g_Whh1p + (size_t)nt * 16 * 8192, 16, sm, acc);
        step_epi(acc, (float*)sm,
                 g_xg1[t & 1], (size_t)G4H,
                 g_c1, g_hA1[(t + 1) & 1], m0, nt, mtl);
    }
}

// ---------------------------------------------------------------------------
// Context input GEMM: xg0 = ctx @ Wih0^T + b0. grid (32, 1024), K=512 (8 p).
// ---------------------------------------------------------------------------
__global__ void __launch_bounds__(256, 2)
ctx_gemm_kernel()
{
    extern __shared__ __align__(16) __half sm[];

    const int nt = blockIdx.x;            // 0..31
    const int mt = blockIdx.y;            // 0..1023
    const int m0 = mt * 64;

    float acc[2][4][4];
    #pragma unroll
    for (int a = 0; a < 2; a++)
        #pragma unroll
        for (int b = 0; b < 4; b++)
            #pragma unroll
            for (int l = 0; l < 4; l++) acc[a][b][l] = 0.f;

    gemm16(g_ctxp + (size_t)mt * 8 * 4096,
           g_Wih0p + (size_t)nt * 8 * 8192, 8, sm, acc);

    bias_epi(acc, g_xg0, G4H, g_b0p, m0, nt * 128);
}

// ---------------------------------------------------------------------------
// Merged preprocessing: z 0-3 weights, z 4 context, z 5 biases + h/c init.
// W blocks [128 n][64 k] (8192 halves); A blocks [64][64] (4096 halves).
// ---------------------------------------------------------------------------
__global__ void pack_all_kernel(
    const float* __restrict__ Wih0, const float* __restrict__ Whh0,
    const float* __restrict__ Wih1, const float* __restrict__ Whh1,
    const float* __restrict__ ctx,
    const float* __restrict__ bih0, const float* __restrict__ bhh0,
    const float* __restrict__ bih1, const float* __restrict__ bhh1,
    const float* __restrict__ init_h)
{
    const int z = blockIdx.z;
    const size_t stride = (size_t)gridDim.x * blockDim.x;
    size_t base = (size_t)blockIdx.x * blockDim.x + threadIdx.x;

    if (z < 4) {
        const float* src = (z == 0) ? Wih0 : (z == 1) ? Whh0
                         : (z == 2) ? Wih1 : Whh1;
        __half* dst = (z == 0) ? g_Wih0p : (z == 1) ? g_Whh0p
                    : (z == 2) ? g_Wih1p : g_Whh1p;
        const int K = (z == 0) ? II : HH;
        const int NKP = K >> 6;
        size_t n = (size_t)G4H * K;
        for (size_t idx = base; idx < n; idx += stride) {
            int blk = (int)(idx >> 13);          // 8192 halves per block
            int wi  = (int)(idx & 8191);
            int nl = wi >> 6, kl = wi & 63;
            int nt = blk / NKP, kp = blk % NKP;
            int p = nt * 128 + nl;
            int k = kp * 64 + kl;
            int j = p >> 2, g = p & 3;
            dst[idx] = __float2half_rn(src[(size_t)(g * HH + j) * K + k]);
        }
    } else if (z == 4) {
        size_t n = (size_t)BB * TT * II;
        for (size_t idx = base; idx < n; idx += stride) {
            int blk = (int)(idx >> 12);          // 4096 halves per block
            int wi  = (int)(idx & 4095);
            int r = wi >> 6, kl = wi & 63;
            int mt = blk >> 3, kp = blk & 7;     // NKP = 8
            size_t row = (size_t)mt * 64 + r;
            g_ctxp[idx] = __float2half_rn(ctx[row * II + kp * 64 + kl]);
        }
    } else {
        for (size_t p = base; p < G4H; p += stride) {
            int j = (int)(p >> 2), g = (int)(p & 3);
            int r = g * HH + j;
            g_b0p[p] = bih0[r] + bhh0[r];
            g_b1p[p] = bih1[r] + bhh1[r];
        }
        for (size_t i = base; i < (size_t)BB * HH; i += stride) {
            int b = (int)(i >> 10), j = (int)(i & 1023);
            size_t idx = (size_t)((b >> 6) * 16 + (j >> 6)) * 4096
                       + (b & 63) * 64 + (j & 63);
            __half hv = __float2half_rn(init_h[i]);
            g_hA0[0][idx] = hv;
            g_hA1[0][idx] = hv;
            g_c0[i] = 0.f;
            g_c1[i] = 0.f;
        }
    }
}

// readout: out[b] = h2_final[b] . W_ro + b_ro   (h2 final in g_hA1[0])
__global__ void readout_kernel(const float* __restrict__ Wro,
                               const float* __restrict__ bro,
                               float* __restrict__ out)
{
    int b = blockIdx.x;
    float s = 0.f;
    for (int j = threadIdx.x; j < HH; j += 128) {
        size_t idx = (size_t)((b >> 6) * 16 + (j >> 6)) * 4096
                   + (b & 63) * 64 + (j & 63);
        s += __half2float(g_hA1[0][idx]) * Wro[j];
    }
    #pragma unroll
    for (int o = 16; o; o >>= 1) s += __shfl_down_sync(0xffffffff, s, o);
    __shared__ float red[4];
    if ((threadIdx.x & 31) == 0) red[threadIdx.x >> 5] = s;
    __syncthreads();
    if (threadIdx.x == 0)
        out[b] = red[0] + red[1] + red[2] + red[3] + bro[0];
}

// ---------------------------------------------------------------------------
extern "C" void kernel_launch(void* const* d_in, const int* in_sizes, int n_in,
                              void* d_out, int out_size)
{
    const float* init_hidden = (const float*)d_in[0];
    const float* context     = (const float*)d_in[1];
    const float* W_ih0       = (const float*)d_in[2];
    const float* W_hh0       = (const float*)d_in[3];
    const float* b_ih0       = (const float*)d_in[4];
    const float* b_hh0       = (const float*)d_in[5];
    const float* W_ih1       = (const float*)d_in[6];
    const float* W_hh1       = (const float*)d_in[7];
    const float* b_ih1       = (const float*)d_in[8];
    const float* b_hh1       = (const float*)d_in[9];
    const float* W_ro        = (const float*)d_in[10];
    const float* b_ro        = (const float*)d_in[11];
    float* out = (float*)d_out;

    cudaFuncSetAttribute(wave_kernel,
        cudaFuncAttributeMaxDynamicSharedMemorySize, SMEMB);
    cudaFuncSetAttribute(ctx_gemm_kernel,
        cudaFuncAttributeMaxDynamicSharedMemorySize, SMEMB);

    // launch 0: merged preprocessing
    pack_all_kernel<<<dim3(1024, 1, 6), 256>>>(
        W_ih0, W_hh0, W_ih1, W_hh1, context,
        b_ih0, b_hh0, b_ih1, b_hh1, init_hidden);

    // launch 1: layer-0 input gates (big parallel GEMM)
    ctx_gemm_kernel<<<dim3(32, (BB * TT) / 64), 256, SMEMB>>>();

    // launches 2..259: wavefront (R7 scheduling: 384 one-tile CTAs)
    const dim3 g_wave(32, 4, 3);
    for (int i = 0; i < NWAVE; i++)
        wave_kernel<<<g_wave, 256, SMEMB>>>(i);

    // readout
    readout_kernel<<<BB, 128>>>(W_ro, b_ro, out);
}